// round 16
// baseline (speedup 1.0000x reference)
#include <cuda_runtime.h>
#include <cuda_fp16.h>
#include <cstdint>

#define C_PAD   1024
#define B_ROWS  16384
#define DIN     1024
#define DOUT    256

// ---------------- scratch (static __device__, no allocation) ----------------
__device__ __align__(16) float g_class_sum[C_PAD * DIN];   // 4 MB
__device__ int   g_icnt[C_PAD];
__device__ float g_total[DIN];
__device__ __align__(16) float g_M2[C_PAD * DOUT];         // 1 MB
__device__ int   g_lbl32 = 0;      // sticky: 1 if labels are int32 (write-1-only)
__device__ __align__(16) __half g_wf16[DOUT * DIN];        // 0.5 MB, W1 in fp16
__device__ int   g_rows[C_PAD * B_ROWS];                   // 64 MB CSR row lists

// ---------------- helpers ----------------------------------------------------
__device__ __forceinline__ int load_label(const void* l, int i, int is64) {
    if (is64) return (int)(((const long long*)l)[i]);
    return ((const int*)l)[i];
}
__device__ __forceinline__ uint32_t smem_u32(const void* p) {
    uint32_t a;
    asm("{ .reg .u64 t; cvta.to.shared.u64 t, %1; cvt.u32.u64 %0, t; }" : "=r"(a) : "l"(p));
    return a;
}
__device__ __forceinline__ void cp16(uint32_t dst, const void* src) {
    asm volatile("cp.async.cg.shared.global [%0], [%1], 16;" :: "r"(dst), "l"(src));
}
#define CP_COMMIT() asm volatile("cp.async.commit_group;" ::: "memory")
#define CP_WAIT1()  asm volatile("cp.async.wait_group 1;" ::: "memory")

__device__ __forceinline__ void ldsm_x4(uint32_t addr, uint32_t* r) {
    asm volatile("ldmatrix.sync.aligned.m8n8.x4.shared.b16 {%0,%1,%2,%3}, [%4];"
                 : "=r"(r[0]), "=r"(r[1]), "=r"(r[2]), "=r"(r[3]) : "r"(addr));
}
__device__ __forceinline__ void mma_f16(float* c, const uint32_t* a, const uint32_t* b) {
    asm volatile(
        "mma.sync.aligned.m16n8k16.row.col.f32.f16.f16.f32 "
        "{%0,%1,%2,%3}, {%4,%5,%6,%7}, {%8,%9}, {%0,%1,%2,%3};"
        : "+f"(c[0]), "+f"(c[1]), "+f"(c[2]), "+f"(c[3])
        : "r"(a[0]), "r"(a[1]), "r"(a[2]), "r"(a[3]), "r"(b[0]), "r"(b[1]));
}
__device__ __forceinline__ uint2 cvt4h(float4 v) {
    __half2 h01 = __floats2half2_rn(v.x, v.y);
    __half2 h23 = __floats2half2_rn(v.z, v.w);
    uint2 r;
    r.x = *(uint32_t*)&h01;
    r.y = *(uint32_t*)&h23;
    return r;
}

// ---------------- k_setup: W1->fp16 + label detect + zeroing -----------------
__global__ void k_setup(const float* __restrict__ W1w, const int* __restrict__ lw) {
    int b = blockIdx.x, t = threadIdx.x;
    if (b < 256) {
        float4 v = ((const float4*)(W1w + (size_t)b * DIN))[t];
        *(uint2*)(g_wf16 + (size_t)b * DIN + 4 * t) = cvt4h(v);
    } else if (b < 288) {
        int i = (b - 256) * 256 + t;
        if (lw[2 * i + 1] != 0) g_lbl32 = 1;   // idempotent on replay
    } else if (b < 292) {
        g_icnt[(b - 288) * 256 + t] = 0;
    } else {
        g_total[(b - 292) * 256 + t] = 0.f;
    }
}

// CSR build
__global__ void k_count(const void* __restrict__ lbl) {
    int i = blockIdx.x * blockDim.x + threadIdx.x;
    int is64 = (g_lbl32 == 0);
    int c = load_label(lbl, i, is64);
    int slot = atomicAdd(&g_icnt[c], 1);
    g_rows[(size_t)c * B_ROWS + slot] = i;
}

// gather-sum: one CTA per class
__global__ __launch_bounds__(256) void k_gather(const float* __restrict__ x) {
    int c = blockIdx.x;
    int t = threadIdx.x;
    int n = g_icnt[c];
    const int* rows = g_rows + (size_t)c * B_ROWS;
    float4 a0 = {0.f, 0.f, 0.f, 0.f};
    float4 a1 = {0.f, 0.f, 0.f, 0.f};
    int r = 0;
    for (; r + 2 <= n; r += 2) {
        int i0 = rows[r], i1 = rows[r + 1];
        float4 v0 = ((const float4*)(x + (size_t)i0 * DIN))[t];
        float4 v1 = ((const float4*)(x + (size_t)i1 * DIN))[t];
        a0.x += v0.x; a0.y += v0.y; a0.z += v0.z; a0.w += v0.w;
        a1.x += v1.x; a1.y += v1.y; a1.z += v1.z; a1.w += v1.w;
    }
    if (r < n) {
        float4 v0 = ((const float4*)(x + (size_t)rows[r] * DIN))[t];
        a0.x += v0.x; a0.y += v0.y; a0.z += v0.z; a0.w += v0.w;
    }
    float4 o;
    o.x = a0.x + a1.x; o.y = a0.y + a1.y;
    o.z = a0.z + a1.z; o.w = a0.w + a1.w;
    ((float4*)(g_class_sum + (size_t)c * DIN))[t] = o;
}

// total_sum over classes. grid (16,16)
__global__ void k_total() {
    int col  = blockIdx.x * 64 + (threadIdx.x & 63);
    int part = threadIdx.x >> 6;
    int c0 = blockIdx.y * 64 + part * 16;
    float s = 0.f;
#pragma unroll
    for (int c = c0; c < c0 + 16; ++c) s += g_class_sum[(size_t)c * DIN + col];
    __shared__ float red[256];
    red[threadIdx.x] = s;
    __syncthreads();
    if (part == 0)
        atomicAdd(&g_total[col], red[threadIdx.x] + red[threadIdx.x + 64] +
                                 red[threadIdx.x + 128] + red[threadIdx.x + 192]);
}

// M2[c] = mean_c @ W2^T + b2
__global__ __launch_bounds__(256) void k_m2(const float* __restrict__ W2w,
                                            const float* __restrict__ W2b) {
    __shared__ float As[32][33];
    __shared__ float Bs[32][68];
    __shared__ float sscale[32];

    int n0 = blockIdx.x * 64;
    int c0 = blockIdx.y * 32;
    int tid = threadIdx.x;

    if (tid < 32) {
        float cnt = (float)g_icnt[c0 + tid];
        float oc = (float)B_ROWS - cnt;
        sscale[tid] = (oc > 0.5f) ? (1.0f / oc) : 0.0f;
    }
    __syncthreads();

    int am = tid >> 3;
    int ak = (tid & 7) * 4;
    int tx = tid & 15, ty = tid >> 4;
    float acc[2][4] = {};

    for (int k0 = 0; k0 < DIN; k0 += 32) {
        float4 t4 = *(const float4*)(g_total + k0 + ak);
        float4 s4 = *(const float4*)(g_class_sum + (size_t)(c0 + am) * DIN + k0 + ak);
        float sc = sscale[am];
        __syncthreads();
        As[ak + 0][am] = (t4.x - s4.x) * sc;
        As[ak + 1][am] = (t4.y - s4.y) * sc;
        As[ak + 2][am] = (t4.z - s4.z) * sc;
        As[ak + 3][am] = (t4.w - s4.w) * sc;
#pragma unroll
        for (int it = 0; it < 2; ++it) {
            int idx = tid + it * 256;
            int bn = idx >> 3;
            int bk = (idx & 7) * 4;
            float4 w4 = *(const float4*)(W2w + (size_t)(n0 + bn) * DIN + k0 + bk);
            Bs[bk + 0][bn] = w4.x;
            Bs[bk + 1][bn] = w4.y;
            Bs[bk + 2][bn] = w4.z;
            Bs[bk + 3][bn] = w4.w;
        }
        __syncthreads();
#pragma unroll
        for (int k = 0; k < 32; ++k) {
            float a0 = As[k][2 * ty + 0];
            float a1 = As[k][2 * ty + 1];
            float4 b = *(const float4*)(&Bs[k][4 * tx]);
            acc[0][0] += a0 * b.x; acc[0][1] += a0 * b.y;
            acc[0][2] += a0 * b.z; acc[0][3] += a0 * b.w;
            acc[1][0] += a1 * b.x; acc[1][1] += a1 * b.y;
            acc[1][2] += a1 * b.z; acc[1][3] += a1 * b.w;
        }
    }
#pragma unroll
    for (int r = 0; r < 2; ++r) {
        int c = c0 + 2 * ty + r;
        int n = n0 + 4 * tx;
        float4 bb = *(const float4*)(W2b + n);
        float4 o;
        o.x = acc[r][0] + bb.x; o.y = acc[r][1] + bb.y;
        o.z = acc[r][2] + bb.z; o.w = acc[r][3] + bb.w;
        *(float4*)(g_M2 + (size_t)c * DOUT + n) = o;
    }
}

// ---------------- k_main_raw: fp16 GEMM only (no M2 dependency) --------------
#define KC       32
#define NC       (DIN / KC)
#define FST      36
#define XF_SZ    (128 * FST * 4)               // 18432 B per x stage
#define AST      40
#define AB_SZ    (128 * AST * 2)               // 10240 B per A fp16 buffer
#define BB_SZ    (256 * AST * 2)               // 20480 B per B fp16 stage
#define BQ_OFF   (3 * XF_SZ)                   // 55296
#define ABUF_OFF (BQ_OFF + 3 * BB_SZ)          // 116736
#define SM_TOT   (ABUF_OFF + 2 * AB_SZ)        // 137216 B

__global__ __launch_bounds__(512, 1) void k_main_raw(const float* __restrict__ x,
                                                     float* __restrict__ out) {
    extern __shared__ char sm[];
    uint32_t smb = smem_u32(sm);
    int tid = threadIdx.x;
    int wid = tid >> 5, lane = tid & 31;
    int wm = wid >> 2, wn = wid & 3;
    int m0 = blockIdx.x * 128;

    int a_r = wm * 32 + (lane & 15);
    int a_k = (lane >> 4) * 8;
    // B x4 map: lanes 0-7/8-15 -> first 8 n-rows (k halves), 16-23/24-31 -> +8 rows
    int b_r4 = wn * 64 + (lane & 7) + (((lane >> 4) & 1) * 8);
    int b_k  = ((lane >> 3) & 1) * 8;

    float acc[2][8][4];
#pragma unroll
    for (int i = 0; i < 2; ++i)
#pragma unroll
        for (int j = 0; j < 8; ++j)
#pragma unroll
            for (int q = 0; q < 4; ++q) acc[i][j][q] = 0.f;

    auto load_stage = [&](int s, int k0) {
        uint32_t xbase = smb + s * XF_SZ;
#pragma unroll
        for (int i = 0; i < 2; ++i) {
            int c = tid + 512 * i;
            int row = c >> 3, kq = c & 7;
            cp16(xbase + row * (FST * 4) + kq * 16,
                 x + (size_t)(m0 + row) * DIN + k0 + 4 * kq);
        }
        uint32_t bbase = smb + BQ_OFF + s * BB_SZ;
#pragma unroll
        for (int i = 0; i < 2; ++i) {
            int c = tid + 512 * i;
            int row = c >> 2, kq = c & 3;
            cp16(bbase + row * (AST * 2) + kq * 16,
                 g_wf16 + (size_t)row * DIN + k0 + 8 * kq);
        }
    };

    auto convert = [&](int src_s, int dst_d) {
        uint32_t fx_off = src_s * XF_SZ;
        uint32_t aoff = ABUF_OFF + dst_d * AB_SZ;
#pragma unroll
        for (int i = 0; i < 2; ++i) {
            int c = tid + 512 * i;
            int row = c >> 3, kq = c & 7;
            float4 v = *(const float4*)(sm + fx_off + row * (FST * 4) + kq * 16);
            *(uint2*)(sm + aoff + row * (AST * 2) + kq * 8) = cvt4h(v);
        }
    };

    load_stage(0, 0);  CP_COMMIT();
    load_stage(1, KC); CP_COMMIT();
    CP_WAIT1();
    convert(0, 0);

    for (int kc = 0; kc < NC; ++kc) {
        int d = kc & 1;
        __syncthreads();

        if (kc + 2 < NC) load_stage((kc + 2) % 3, (kc + 2) * KC);
        CP_COMMIT();

        uint32_t AB = smb + ABUF_OFF + d * AB_SZ;
        uint32_t BB = smb + BQ_OFF + (kc % 3) * BB_SZ;

#pragma unroll
        for (int kk = 0; kk < KC; kk += 16) {
            uint32_t ah[2][4];
#pragma unroll
            for (int mi = 0; mi < 2; ++mi) {
                uint32_t off = (uint32_t)((a_r + mi * 16) * AST + kk + a_k) * 2;
                ldsm_x4(AB + off, ah[mi]);
            }
#pragma unroll
            for (int p = 0; p < 4; ++p) {        // ni pairs (2p, 2p+1)
                uint32_t boff = (uint32_t)((b_r4 + p * 16) * AST + kk + b_k) * 2;
                uint32_t bq[4];
                ldsm_x4(BB + boff, bq);
#pragma unroll
                for (int mi = 0; mi < 2; ++mi) {
                    mma_f16(acc[mi][2 * p + 0], ah[mi], bq);
                    mma_f16(acc[mi][2 * p + 1], ah[mi], bq + 2);
                }
            }
        }

        if (kc + 1 < NC) {
            CP_WAIT1();
            convert((kc + 1) % 3, d ^ 1);
        }
    }

    // store raw GEMM result
    int nlo = (lane & 3) * 2;
    int rbase = m0 + wm * 32 + (lane >> 2);
#pragma unroll
    for (int mi = 0; mi < 2; ++mi) {
        int r0 = rbase + mi * 16;
        int r1 = r0 + 8;
        float* o0 = out + (size_t)r0 * DOUT;
        float* o1 = out + (size_t)r1 * DOUT;
#pragma unroll
        for (int ni = 0; ni < 8; ++ni) {
            int n = wn * 64 + ni * 8 + nlo;
            float2 vA, vB;
            vA.x = acc[mi][ni][0]; vA.y = acc[mi][ni][1];
            vB.x = acc[mi][ni][2]; vB.y = acc[mi][ni][3];
            *(float2*)(o0 + n) = vA;
            *(float2*)(o1 + n) = vB;
        }
    }
}

// epilogue: out[m][n] += b1[n] + M2[label[m]][n]
__global__ __launch_bounds__(256) void k_epi(const void* __restrict__ lbl,
                                             const float* __restrict__ W1b,
                                             float* __restrict__ out) {
    int t = threadIdx.x;
    int row = blockIdx.x * 4 + (t >> 6);
    int n = (t & 63) * 4;
    int is64 = (g_lbl32 == 0);
    int c = load_label(lbl, row, is64);
    float4 bb = *(const float4*)(W1b + n);
    float4 mm = *(const float4*)(g_M2 + (size_t)c * DOUT + n);
    float4* op = (float4*)(out + (size_t)row * DOUT + n);
    float4 o = *op;
    o.x += bb.x + mm.x; o.y += bb.y + mm.y;
    o.z += bb.z + mm.z; o.w += bb.w + mm.w;
    *op = o;
}

// ---------------- launch: fork-join overlap ----------------------------------
extern "C" void kernel_launch(void* const* d_in, const int* in_sizes, int n_in,
                              void* d_out, int out_size) {
    const float* x   = (const float*)d_in[0];
    const void*  lbl = d_in[1];
    const float* W1w = (const float*)d_in[2];
    const float* W1b = (const float*)d_in[3];
    const float* W2w = (const float*)d_in[4];
    const float* W2b = (const float*)d_in[5];
    float* out = (float*)d_out;

    // one-time infra (no device memory): side stream + fork/join events
    static cudaStream_t s2 = nullptr;
    static cudaEvent_t e1 = nullptr, e2 = nullptr;
    if (s2 == nullptr) {
        cudaStreamCreateWithFlags(&s2, cudaStreamNonBlocking);
        cudaEventCreateWithFlags(&e1, cudaEventDisableTiming);
        cudaEventCreateWithFlags(&e2, cudaEventDisableTiming);
        cudaFuncSetAttribute(k_main_raw, cudaFuncAttributeMaxDynamicSharedMemorySize, SM_TOT);
    }

    k_setup<<<296, 256>>>(W1w, (const int*)lbl);

    // fork: reduction chain on s2, GEMM on main stream
    cudaEventRecord(e1, 0);
    cudaStreamWaitEvent(s2, e1, 0);
    k_count<<<B_ROWS / 256, 256, 0, s2>>>(lbl);
    k_gather<<<C_PAD, 256, 0, s2>>>(x);
    k_total<<<dim3(16, 16), 256, 0, s2>>>();
    k_m2<<<dim3(4, 32), 256, 0, s2>>>(W2w, W2b);
    cudaEventRecord(e2, s2);

    k_main_raw<<<128, 512, SM_TOT>>>(x, out);

    // join, then epilogue
    cudaStreamWaitEvent(0, e2, 0);
    k_epi<<<B_ROWS / 4, 256>>>(lbl, W1b, out);
}

// round 17
// speedup vs baseline: 1.7291x; 1.7291x over previous
#include <cuda_runtime.h>
#include <cuda_fp16.h>
#include <cstdint>

#define C_PAD   1024
#define B_ROWS  16384
#define DIN     1024
#define DOUT    256

// ---------------- scratch (static __device__, no allocation) ----------------
__device__ __align__(16) float g_class_sum[C_PAD * DIN];   // 4 MB
__device__ int   g_icnt[C_PAD];
__device__ float g_total[DIN];
__device__ __align__(16) float g_M2[C_PAD * DOUT];         // 1 MB
__device__ int   g_lbl32 = 0;      // sticky: 1 if labels are int32 (write-1-only)
__device__ __align__(16) __half g_wf16[DOUT * DIN];        // 0.5 MB, W1 in fp16
__device__ int   g_rows[C_PAD * B_ROWS];                   // 64 MB CSR row lists

// ---------------- helpers ----------------------------------------------------
__device__ __forceinline__ int load_label(const void* l, int i, int is64) {
    if (is64) return (int)(((const long long*)l)[i]);
    return ((const int*)l)[i];
}
__device__ __forceinline__ uint32_t smem_u32(const void* p) {
    uint32_t a;
    asm("{ .reg .u64 t; cvta.to.shared.u64 t, %1; cvt.u32.u64 %0, t; }" : "=r"(a) : "l"(p));
    return a;
}
__device__ __forceinline__ void cp16(uint32_t dst, const void* src) {
    asm volatile("cp.async.cg.shared.global [%0], [%1], 16;" :: "r"(dst), "l"(src));
}
#define CP_COMMIT() asm volatile("cp.async.commit_group;" ::: "memory")
#define CP_WAIT1()  asm volatile("cp.async.wait_group 1;" ::: "memory")

__device__ __forceinline__ void ldsm_x4(uint32_t addr, uint32_t* r) {
    asm volatile("ldmatrix.sync.aligned.m8n8.x4.shared.b16 {%0,%1,%2,%3}, [%4];"
                 : "=r"(r[0]), "=r"(r[1]), "=r"(r[2]), "=r"(r[3]) : "r"(addr));
}
__device__ __forceinline__ void mma_f16(float* c, const uint32_t* a, const uint32_t* b) {
    asm volatile(
        "mma.sync.aligned.m16n8k16.row.col.f32.f16.f16.f32 "
        "{%0,%1,%2,%3}, {%4,%5,%6,%7}, {%8,%9}, {%0,%1,%2,%3};"
        : "+f"(c[0]), "+f"(c[1]), "+f"(c[2]), "+f"(c[3])
        : "r"(a[0]), "r"(a[1]), "r"(a[2]), "r"(a[3]), "r"(b[0]), "r"(b[1]));
}
__device__ __forceinline__ uint2 cvt4h(float4 v) {
    __half2 h01 = __floats2half2_rn(v.x, v.y);
    __half2 h23 = __floats2half2_rn(v.z, v.w);
    uint2 r;
    r.x = *(uint32_t*)&h01;
    r.y = *(uint32_t*)&h23;
    return r;
}

// ---------------- k_setup: W1->fp16 + label detect + zeroing -----------------
__global__ void k_setup(const float* __restrict__ W1w, const int* __restrict__ lw) {
    int b = blockIdx.x, t = threadIdx.x;
    if (b < 256) {
        float4 v = ((const float4*)(W1w + (size_t)b * DIN))[t];
        *(uint2*)(g_wf16 + (size_t)b * DIN + 4 * t) = cvt4h(v);
    } else if (b < 288) {
        int i = (b - 256) * 256 + t;
        if (lw[2 * i + 1] != 0) g_lbl32 = 1;   // idempotent on replay
    } else if (b < 292) {
        g_icnt[(b - 288) * 256 + t] = 0;
    } else {
        g_total[(b - 292) * 256 + t] = 0.f;
    }
}

// CSR build
__global__ void k_count(const void* __restrict__ lbl) {
    int i = blockIdx.x * blockDim.x + threadIdx.x;
    int is64 = (g_lbl32 == 0);
    int c = load_label(lbl, i, is64);
    int slot = atomicAdd(&g_icnt[c], 1);
    g_rows[(size_t)c * B_ROWS + slot] = i;
}

// gather-sum: one CTA per class
__global__ __launch_bounds__(256) void k_gather(const float* __restrict__ x) {
    int c = blockIdx.x;
    int t = threadIdx.x;
    int n = g_icnt[c];
    const int* rows = g_rows + (size_t)c * B_ROWS;
    float4 a0 = {0.f, 0.f, 0.f, 0.f};
    float4 a1 = {0.f, 0.f, 0.f, 0.f};
    int r = 0;
    for (; r + 2 <= n; r += 2) {
        int i0 = rows[r], i1 = rows[r + 1];
        float4 v0 = ((const float4*)(x + (size_t)i0 * DIN))[t];
        float4 v1 = ((const float4*)(x + (size_t)i1 * DIN))[t];
        a0.x += v0.x; a0.y += v0.y; a0.z += v0.z; a0.w += v0.w;
        a1.x += v1.x; a1.y += v1.y; a1.z += v1.z; a1.w += v1.w;
    }
    if (r < n) {
        float4 v0 = ((const float4*)(x + (size_t)rows[r] * DIN))[t];
        a0.x += v0.x; a0.y += v0.y; a0.z += v0.z; a0.w += v0.w;
    }
    float4 o;
    o.x = a0.x + a1.x; o.y = a0.y + a1.y;
    o.z = a0.z + a1.z; o.w = a0.w + a1.w;
    ((float4*)(g_class_sum + (size_t)c * DIN))[t] = o;
}

// total_sum over classes. grid (16,16)
__global__ void k_total() {
    int col  = blockIdx.x * 64 + (threadIdx.x & 63);
    int part = threadIdx.x >> 6;
    int c0 = blockIdx.y * 64 + part * 16;
    float s = 0.f;
#pragma unroll
    for (int c = c0; c < c0 + 16; ++c) s += g_class_sum[(size_t)c * DIN + col];
    __shared__ float red[256];
    red[threadIdx.x] = s;
    __syncthreads();
    if (part == 0)
        atomicAdd(&g_total[col], red[threadIdx.x] + red[threadIdx.x + 64] +
                                 red[threadIdx.x + 128] + red[threadIdx.x + 192]);
}

// M2[c] = mean_c @ W2^T + b2
__global__ __launch_bounds__(256) void k_m2(const float* __restrict__ W2w,
                                            const float* __restrict__ W2b) {
    __shared__ float As[32][33];
    __shared__ float Bs[32][68];
    __shared__ float sscale[32];

    int n0 = blockIdx.x * 64;
    int c0 = blockIdx.y * 32;
    int tid = threadIdx.x;

    if (tid < 32) {
        float cnt = (float)g_icnt[c0 + tid];
        float oc = (float)B_ROWS - cnt;
        sscale[tid] = (oc > 0.5f) ? (1.0f / oc) : 0.0f;
    }
    __syncthreads();

    int am = tid >> 3;
    int ak = (tid & 7) * 4;
    int tx = tid & 15, ty = tid >> 4;
    float acc[2][4] = {};

    for (int k0 = 0; k0 < DIN; k0 += 32) {
        float4 t4 = *(const float4*)(g_total + k0 + ak);
        float4 s4 = *(const float4*)(g_class_sum + (size_t)(c0 + am) * DIN + k0 + ak);
        float sc = sscale[am];
        __syncthreads();
        As[ak + 0][am] = (t4.x - s4.x) * sc;
        As[ak + 1][am] = (t4.y - s4.y) * sc;
        As[ak + 2][am] = (t4.z - s4.z) * sc;
        As[ak + 3][am] = (t4.w - s4.w) * sc;
#pragma unroll
        for (int it = 0; it < 2; ++it) {
            int idx = tid + it * 256;
            int bn = idx >> 3;
            int bk = (idx & 7) * 4;
            float4 w4 = *(const float4*)(W2w + (size_t)(n0 + bn) * DIN + k0 + bk);
            Bs[bk + 0][bn] = w4.x;
            Bs[bk + 1][bn] = w4.y;
            Bs[bk + 2][bn] = w4.z;
            Bs[bk + 3][bn] = w4.w;
        }
        __syncthreads();
#pragma unroll
        for (int k = 0; k < 32; ++k) {
            float a0 = As[k][2 * ty + 0];
            float a1 = As[k][2 * ty + 1];
            float4 b = *(const float4*)(&Bs[k][4 * tx]);
            acc[0][0] += a0 * b.x; acc[0][1] += a0 * b.y;
            acc[0][2] += a0 * b.z; acc[0][3] += a0 * b.w;
            acc[1][0] += a1 * b.x; acc[1][1] += a1 * b.y;
            acc[1][2] += a1 * b.z; acc[1][3] += a1 * b.w;
        }
    }
#pragma unroll
    for (int r = 0; r < 2; ++r) {
        int c = c0 + 2 * ty + r;
        int n = n0 + 4 * tx;
        float4 bb = *(const float4*)(W2b + n);
        float4 o;
        o.x = acc[r][0] + bb.x; o.y = acc[r][1] + bb.y;
        o.z = acc[r][2] + bb.z; o.w = acc[r][3] + bb.w;
        *(float4*)(g_M2 + (size_t)c * DOUT + n) = o;
    }
}

// ---------------- k_main: single-pass fp16 GEMM + fused epilogue -------------
#define KC       32
#define NC       (DIN / KC)
#define FST      36
#define XF_SZ    (128 * FST * 4)               // 18432 B per x stage
#define AST      40
#define AB_SZ    (128 * AST * 2)               // 10240 B per A fp16 buffer
#define BB_SZ    (256 * AST * 2)               // 20480 B per B fp16 stage
#define BQ_OFF   (3 * XF_SZ)                   // 55296
#define ABUF_OFF (BQ_OFF + 3 * BB_SZ)          // 116736
#define SM_TOT   (ABUF_OFF + 2 * AB_SZ)        // 137216 B

__global__ __launch_bounds__(512, 1) void k_main(const float* __restrict__ x,
                                                 const void* __restrict__ lbl,
                                                 const float* __restrict__ W1b,
                                                 float* __restrict__ out) {
    extern __shared__ char sm[];
    uint32_t smb = smem_u32(sm);
    int tid = threadIdx.x;
    int wid = tid >> 5, lane = tid & 31;
    int wm = wid >> 2, wn = wid & 3;        // warp grid 4(M) x 4(N), 32x64 per warp
    int m0 = blockIdx.x * 128;

    int a_r = wm * 32 + (lane & 15);
    int a_k = (lane >> 4) * 8;
    // B x4 map: lane groups 0-7/8-15 -> k-halves of rows b..b+7; 16-23/24-31 -> rows b+8..b+15
    int b_r4 = wn * 64 + (lane & 7) + (((lane >> 4) & 1) * 8);
    int b_k  = ((lane >> 3) & 1) * 8;

    float acc[2][8][4];
#pragma unroll
    for (int i = 0; i < 2; ++i)
#pragma unroll
        for (int j = 0; j < 8; ++j)
#pragma unroll
            for (int q = 0; q < 4; ++q) acc[i][j][q] = 0.f;

    auto load_stage = [&](int s, int k0) {
        uint32_t xbase = smb + s * XF_SZ;
#pragma unroll
        for (int i = 0; i < 2; ++i) {
            int c = tid + 512 * i;
            int row = c >> 3, kq = c & 7;
            cp16(xbase + row * (FST * 4) + kq * 16,
                 x + (size_t)(m0 + row) * DIN + k0 + 4 * kq);
        }
        uint32_t bbase = smb + BQ_OFF + s * BB_SZ;
#pragma unroll
        for (int i = 0; i < 2; ++i) {
            int c = tid + 512 * i;
            int row = c >> 2, kq = c & 3;
            cp16(bbase + row * (AST * 2) + kq * 16,
                 g_wf16 + (size_t)row * DIN + k0 + 8 * kq);
        }
    };

    auto convert = [&](int src_s, int dst_d) {
        uint32_t fx_off = src_s * XF_SZ;
        uint32_t aoff = ABUF_OFF + dst_d * AB_SZ;
#pragma unroll
        for (int i = 0; i < 2; ++i) {
            int c = tid + 512 * i;
            int row = c >> 3, kq = c & 7;
            float4 v = *(const float4*)(sm + fx_off + row * (FST * 4) + kq * 16);
            *(uint2*)(sm + aoff + row * (AST * 2) + kq * 8) = cvt4h(v);
        }
    };

    load_stage(0, 0);  CP_COMMIT();
    load_stage(1, KC); CP_COMMIT();
    CP_WAIT1();
    convert(0, 0);

    for (int kc = 0; kc < NC; ++kc) {
        int d = kc & 1;
        __syncthreads();

        if (kc + 2 < NC) load_stage((kc + 2) % 3, (kc + 2) * KC);
        CP_COMMIT();

        uint32_t AB = smb + ABUF_OFF + d * AB_SZ;
        uint32_t BB = smb + BQ_OFF + (kc % 3) * BB_SZ;

#pragma unroll
        for (int kk = 0; kk < KC; kk += 16) {
            uint32_t ah[2][4];
#pragma unroll
            for (int mi = 0; mi < 2; ++mi) {
                uint32_t off = (uint32_t)((a_r + mi * 16) * AST + kk + a_k) * 2;
                ldsm_x4(AB + off, ah[mi]);
            }
#pragma unroll
            for (int p = 0; p < 4; ++p) {        // ni pairs (2p, 2p+1)
                uint32_t boff = (uint32_t)((b_r4 + p * 16) * AST + kk + b_k) * 2;
                uint32_t bq[4];
                ldsm_x4(BB + boff, bq);
#pragma unroll
                for (int mi = 0; mi < 2; ++mi) {
                    mma_f16(acc[mi][2 * p + 0], ah[mi], bq);
                    mma_f16(acc[mi][2 * p + 1], ah[mi], bq + 2);
                }
            }
        }

        if (kc + 1 < NC) {
            CP_WAIT1();
            convert((kc + 1) % 3, d ^ 1);
        }
    }

    // fused epilogue: + b1[n] + M2[label[m]][n]
    int is64 = (g_lbl32 == 0);
    int nlo = (lane & 3) * 2;
    int rbase = m0 + wm * 32 + (lane >> 2);

    float2 bb[8];
#pragma unroll
    for (int ni = 0; ni < 8; ++ni)
        bb[ni] = *(const float2*)(W1b + wn * 64 + ni * 8 + nlo);

#pragma unroll
    for (int mi = 0; mi < 2; ++mi) {
        int r0 = rbase + mi * 16;
        int r1 = r0 + 8;
        int c0 = load_label(lbl, r0, is64);
        int c1 = load_label(lbl, r1, is64);
        const float* m2r0 = g_M2 + (size_t)c0 * DOUT;
        const float* m2r1 = g_M2 + (size_t)c1 * DOUT;
        float* o0 = out + (size_t)r0 * DOUT;
        float* o1 = out + (size_t)r1 * DOUT;
#pragma unroll
        for (int ni = 0; ni < 8; ++ni) {
            int n = wn * 64 + ni * 8 + nlo;
            float2 mA = *(const float2*)(m2r0 + n);
            float2 mB = *(const float2*)(m2r1 + n);
            float2 vA, vB;
            vA.x = acc[mi][ni][0] + bb[ni].x + mA.x;
            vA.y = acc[mi][ni][1] + bb[ni].y + mA.y;
            vB.x = acc[mi][ni][2] + bb[ni].x + mB.x;
            vB.y = acc[mi][ni][3] + bb[ni].y + mB.y;
            *(float2*)(o0 + n) = vA;
            *(float2*)(o1 + n) = vB;
        }
    }
}

// ---------------- launch: serial (proven 116.8 us structure) -----------------
extern "C" void kernel_launch(void* const* d_in, const int* in_sizes, int n_in,
                              void* d_out, int out_size) {
    const float* x   = (const float*)d_in[0];
    const void*  lbl = d_in[1];
    const float* W1w = (const float*)d_in[2];
    const float* W1b = (const float*)d_in[3];
    const float* W2w = (const float*)d_in[4];
    const float* W2b = (const float*)d_in[5];
    float* out = (float*)d_out;

    cudaFuncSetAttribute(k_main, cudaFuncAttributeMaxDynamicSharedMemorySize, SM_TOT);

    k_setup<<<296, 256>>>(W1w, (const int*)lbl);
    k_count<<<B_ROWS / 256, 256>>>(lbl);
    k_gather<<<C_PAD, 256>>>(x);
    k_total<<<dim3(16, 16), 256>>>();
    k_m2<<<dim3(4, 32), 256>>>(W2w, W2b);
    k_main<<<128, 512, SM_TOT>>>(x, lbl, W1b, out);
}